// round 16
// baseline (speedup 1.0000x reference)
#include <cuda_runtime.h>
#include <cstdint>

#define N_NODES 50000
#define N_EDGES 800000
#define IN_DIM 64
#define EDGE_DIM 32
#define OUT_DIM 64
#define CAP 64       // bucket capacity; Poisson(16): P(deg>64) ~ 1e-21
#define NPB_G 32     // nodes per block (2 row-groups x 16 rows)
#define A_STRIDE 164 // 160 + 4 pad floats; conflict-free MMA fragment reads

// ---- scratch (static device globals: allocation-free) ----
__device__ int  g_deg[N_NODES];
__device__ int2 g_adj[(size_t)N_NODES * CAP];   // (src, edge_id) per-dst bucket
__device__ int  g_is64;

// Fused: zero degrees + detect edge_index dtype (int64 => odd 32-bit words all 0).
__global__ void k_init(const int* __restrict__ ei32) {
    int i = blockIdx.x * blockDim.x + threadIdx.x;
    if (i < N_NODES) g_deg[i] = 0;
    if (blockIdx.x == 0) {
        __shared__ int nz;
        if (threadIdx.x == 0) nz = 0;
        __syncthreads();
        if (ei32[2 * threadIdx.x + 1] != 0) atomicAdd(&nz, 1);
        __syncthreads();
        if (threadIdx.x == 0) g_is64 = (nz == 0) ? 1 : 0;
    }
}

// Single-pass bucket scatter.
__global__ void k_scatter(const void* __restrict__ ei) {
    int e = blockIdx.x * blockDim.x + threadIdx.x;
    if (e < N_EDGES) {
        int src, dst;
        if (g_is64) {
            src = (int)((const long long*)ei)[e];
            dst = (int)((const long long*)ei)[N_EDGES + e];
        } else {
            src = ((const int*)ei)[e];
            dst = ((const int*)ei)[N_EDGES + e];
        }
        src = min(max(src, 0), N_NODES - 1);
        dst = min(max(dst, 0), N_NODES - 1);
        int pos = atomicAdd(&g_deg[dst], 1);
        if (pos < CAP) g_adj[(size_t)dst * CAP + pos] = make_int2(src, e);
    }
}

// ---- tf32 helpers ----
__device__ __forceinline__ uint32_t f32_to_tf32(float f) {
    uint32_t u;
    asm("cvt.rna.tf32.f32 %0, %1;" : "=r"(u) : "f"(f));
    return u;
}
__device__ __forceinline__ void split_tf32(float f, uint32_t& hi, uint32_t& lo) {
    hi = f32_to_tf32(f);
    lo = f32_to_tf32(f - __uint_as_float(hi));
}
__device__ __forceinline__ void mma_16n8k8(
    float& c0, float& c1, float& c2, float& c3,
    uint32_t a0, uint32_t a1, uint32_t a2, uint32_t a3,
    uint32_t b0, uint32_t b1)
{
    asm("mma.sync.aligned.m16n8k8.row.col.f32.tf32.tf32.f32 "
        "{%0,%1,%2,%3}, {%4,%5,%6,%7}, {%8,%9}, {%0,%1,%2,%3};"
        : "+f"(c0), "+f"(c1), "+f"(c2), "+f"(c3)
        : "r"(a0), "r"(a1), "r"(a2), "r"(a3), "r"(b0), "r"(b1));
}

// FUSED gather + tensor-core GEMM.
// Phase 1: stage x rows (coalesced) into s_a cols 0..63.
// Phase 2: 4 warps gather 8 nodes each (R10-proven pipelined loop), writing
//          S1/deg, S2/deg DIRECTLY into s_a cols 64..159 (no gmem roundtrip).
// Phase 3: R15-proven 3xTF32 MMA gemm: out = A[32,160] @ W + biases.
__global__ void __launch_bounds__(128) k_fused(
    const float* __restrict__ x,
    const float* __restrict__ ea,
    const float* __restrict__ msg_w,     // [96,64]
    const float* __restrict__ msg_b,
    const float* __restrict__ self_w,    // [64,64]
    const float* __restrict__ self_b,
    float* __restrict__ out)
{
    __shared__ float s_a[NPB_G * A_STRIDE];   // 21.0 KB
    __shared__ float s_deg[NPB_G];

    const int tid  = threadIdx.x;
    const int lane = tid & 31;
    const int warp = tid >> 5;
    const int blk_node0 = blockIdx.x * NPB_G;

    // ---- Phase 1: stage x part (cols 0..63) ----
    for (int idx = tid; idx < NPB_G * 16; idx += 128) {
        const int row = idx >> 4;
        const int c4  = idx & 15;
        const int node = blk_node0 + row;
        float4 v = make_float4(0.f, 0.f, 0.f, 0.f);
        if (node < N_NODES)
            v = *reinterpret_cast<const float4*>(x + (size_t)node * IN_DIM + c4 * 4);
        *reinterpret_cast<float4*>(s_a + row * A_STRIDE + c4 * 4) = v;
    }

    // ---- Phase 2: gather, 8 nodes per warp ----
    #pragma unroll
    for (int t = 0; t < 8; ++t) {
        const int row  = warp * 8 + t;
        const int node = blk_node0 + row;
        float a0 = 0.f, b0 = 0.f, c0 = 0.f;
        float a1 = 0.f, b1 = 0.f, c1 = 0.f;
        int true_deg = 0;
        if (node < N_NODES) {
            true_deg = g_deg[node];
            const int d = min(true_deg, CAP);
            const size_t abase = (size_t)node * CAP;
            int j = 0;
            #pragma unroll 4
            for (; j + 2 <= d; j += 2) {
                const int2 e0 = __ldcs(&g_adj[abase + j]);
                const int2 e1 = __ldcs(&g_adj[abase + j + 1]);
                const float2 xv0 = *reinterpret_cast<const float2*>(x + (size_t)e0.x * IN_DIM + 2 * lane);
                const float2 xv1 = *reinterpret_cast<const float2*>(x + (size_t)e1.x * IN_DIM + 2 * lane);
                const float ev0 = __ldcs(ea + (size_t)e0.y * EDGE_DIM + lane);
                const float ev1 = __ldcs(ea + (size_t)e1.y * EDGE_DIM + lane);
                a0 += xv0.x;  b0 += xv0.y;  c0 += ev0;
                a1 += xv1.x;  b1 += xv1.y;  c1 += ev1;
            }
            if (j < d) {
                const int2 e0 = __ldcs(&g_adj[abase + j]);
                const float2 xv0 = *reinterpret_cast<const float2*>(x + (size_t)e0.x * IN_DIM + 2 * lane);
                a0 += xv0.x;  b0 += xv0.y;
                c0 += __ldcs(ea + (size_t)e0.y * EDGE_DIM + lane);
            }
        }
        const float inv = 1.f / fmaxf((float)true_deg, 1.f);
        float* r = s_a + row * A_STRIDE;
        r[64 + 2 * lane]     = (a0 + a1) * inv;
        r[64 + 2 * lane + 1] = (b0 + b1) * inv;
        r[128 + lane]        = (c0 + c1) * inv;
        if (lane == 0) s_deg[row] = (float)true_deg;
    }
    __syncthreads();

    // ---- Phase 3: gemm (R15-proven) ----
    const int rg  = warp & 1;             // row group 0..1
    const int nh  = warp >> 1;            // n-half 0..1
    const int wr  = rg * 16;
    const int gid = lane >> 2;            // groupID 0..7
    const int tig = lane & 3;             // threadID_in_group 0..3

    const int row0 = wr + gid;
    const int row1 = row0 + 8;
    const float m0 = (s_deg[row0] > 0.f) ? 1.f : 0.f;
    const float m1 = (s_deg[row1] > 0.f) ? 1.f : 0.f;

    float acc[4][4];
    #pragma unroll
    for (int n = 0; n < 4; ++n) {
        const int col = nh * 32 + n * 8 + tig * 2;
        acc[n][0] = self_b[col]     + m0 * msg_b[col];
        acc[n][1] = self_b[col + 1] + m0 * msg_b[col + 1];
        acc[n][2] = self_b[col]     + m1 * msg_b[col];
        acc[n][3] = self_b[col + 1] + m1 * msg_b[col + 1];
    }

    #pragma unroll 2
    for (int kt = 0; kt < 20; ++kt) {
        const int k0 = kt * 8;
        const float fa0 = s_a[row0 * A_STRIDE + k0 + tig];
        const float fa1 = s_a[row1 * A_STRIDE + k0 + tig];
        const float fa2 = s_a[row0 * A_STRIDE + k0 + tig + 4];
        const float fa3 = s_a[row1 * A_STRIDE + k0 + tig + 4];
        uint32_t a0h, a0l, a1h, a1l, a2h, a2l, a3h, a3l;
        split_tf32(fa0, a0h, a0l);
        split_tf32(fa1, a1h, a1l);
        split_tf32(fa2, a2h, a2l);
        split_tf32(fa3, a3h, a3l);

        const float* wsrc = (k0 < IN_DIM) ? (self_w + k0 * OUT_DIM)
                                          : (msg_w + (k0 - IN_DIM) * OUT_DIM);
        #pragma unroll
        for (int n = 0; n < 4; ++n) {
            const int bcol = nh * 32 + n * 8 + gid;
            const float fb0 = __ldg(wsrc + tig * OUT_DIM + bcol);        // k = tig
            const float fb1 = __ldg(wsrc + (tig + 4) * OUT_DIM + bcol);  // k = tig+4
            uint32_t b0h, b0l, b1h, b1l;
            split_tf32(fb0, b0h, b0l);
            split_tf32(fb1, b1h, b1l);
            // 3xTF32: hi*hi + hi*lo + lo*hi
            mma_16n8k8(acc[n][0], acc[n][1], acc[n][2], acc[n][3],
                       a0h, a1h, a2h, a3h, b0h, b1h);
            mma_16n8k8(acc[n][0], acc[n][1], acc[n][2], acc[n][3],
                       a0h, a1h, a2h, a3h, b0l, b1l);
            mma_16n8k8(acc[n][0], acc[n][1], acc[n][2], acc[n][3],
                       a0l, a1l, a2l, a3l, b0h, b1h);
        }
    }

    const int n0g = blk_node0 + row0;
    const int n1g = blk_node0 + row1;
    #pragma unroll
    for (int n = 0; n < 4; ++n) {
        const int col = nh * 32 + n * 8 + tig * 2;
        if (n0g < N_NODES)
            *reinterpret_cast<float2*>(out + (size_t)n0g * OUT_DIM + col) =
                make_float2(acc[n][0], acc[n][1]);
        if (n1g < N_NODES)
            *reinterpret_cast<float2*>(out + (size_t)n1g * OUT_DIM + col) =
                make_float2(acc[n][2], acc[n][3]);
    }
}

extern "C" void kernel_launch(void* const* d_in, const int* in_sizes, int n_in,
                              void* d_out, int out_size) {
    // Identify inputs by element count (robust to metadata ordering):
    const float* x = 0; const void* ei = 0; const float* ea = 0;
    const float* msg_w = 0; const float* self_w = 0;
    const float* msg_b = 0; const float* self_b = 0;
    for (int i = 0; i < n_in; ++i) {
        const int sz = in_sizes[i];
        if      (sz == N_NODES * IN_DIM)              x      = (const float*)d_in[i];
        else if (sz == 2 * N_EDGES)                   ei     = d_in[i];
        else if (sz == N_EDGES * EDGE_DIM)            ea     = (const float*)d_in[i];
        else if (sz == (IN_DIM + EDGE_DIM) * OUT_DIM) msg_w  = (const float*)d_in[i];
        else if (sz == IN_DIM * OUT_DIM)              self_w = (const float*)d_in[i];
        else if (sz == OUT_DIM) {
            if (!msg_b) msg_b = (const float*)d_in[i];
            else        self_b = (const float*)d_in[i];
        }
    }
    float* out = (float*)d_out;

    k_init<<<(N_NODES + 255) / 256, 256>>>((const int*)ei);
    k_scatter<<<(N_EDGES + 255) / 256, 256>>>(ei);
    k_fused<<<(N_NODES + NPB_G - 1) / NPB_G, 128>>>(x, ea, msg_w, msg_b, self_w, self_b, out);
}

// round 17
// speedup vs baseline: 1.1392x; 1.1392x over previous
#include <cuda_runtime.h>
#include <cstdint>

#define N_NODES 50000
#define N_EDGES 800000
#define IN_DIM 64
#define EDGE_DIM 32
#define OUT_DIM 64
#define CAP 64       // bucket capacity; Poisson(16): P(deg>64) ~ 1e-21
#define NPB_G 32     // nodes per block in k_gemm (2 row-groups x 16 rows)
#define A_STRIDE 164 // 160 + 4 pad floats; conflict-free MMA fragment reads

// ---- scratch (static device globals: allocation-free) ----
__device__ int   g_deg[N_NODES];
__device__ int2  g_adj[(size_t)N_NODES * CAP];   // (src, edge_id) per-dst bucket
__device__ float g_msgin[(size_t)N_NODES * 96];  // [S1/deg (64) | S2/deg (32)]
__device__ int   g_is64;

// Fused: zero degrees + detect edge_index dtype (int64 => odd 32-bit words all 0).
__global__ void k_init(const int* __restrict__ ei32) {
    int i = blockIdx.x * blockDim.x + threadIdx.x;
    if (i < N_NODES) g_deg[i] = 0;
    if (blockIdx.x == 0) {
        __shared__ int nz;
        if (threadIdx.x == 0) nz = 0;
        __syncthreads();
        if (ei32[2 * threadIdx.x + 1] != 0) atomicAdd(&nz, 1);
        __syncthreads();
        if (threadIdx.x == 0) g_is64 = (nz == 0) ? 1 : 0;
    }
}

// Single-pass bucket scatter.
__global__ void k_scatter(const void* __restrict__ ei) {
    int e = blockIdx.x * blockDim.x + threadIdx.x;
    if (e < N_EDGES) {
        int src, dst;
        if (g_is64) {
            src = (int)((const long long*)ei)[e];
            dst = (int)((const long long*)ei)[N_EDGES + e];
        } else {
            src = ((const int*)ei)[e];
            dst = ((const int*)ei)[N_EDGES + e];
        }
        src = min(max(src, 0), N_NODES - 1);
        dst = min(max(dst, 0), N_NODES - 1);
        int pos = atomicAdd(&g_deg[dst], 1);
        if (pos < CAP) g_adj[(size_t)dst * CAP + pos] = make_int2(src, e);
    }
}

// Gather (R10-proven): one warp per node, 2-edge pipelining, dual accumulators,
// __ldcs on single-use streams to preserve L2 for the hot x gather.
__global__ void __launch_bounds__(256) k_gather(
    const float* __restrict__ x,
    const float* __restrict__ ea)
{
    const int gw   = (blockIdx.x * 256 + threadIdx.x) >> 5;
    const int lane = threadIdx.x & 31;
    if (gw >= N_NODES) return;
    const int node = gw;
    const int true_deg = g_deg[node];
    const int d = min(true_deg, CAP);
    const size_t abase = (size_t)node * CAP;

    float a0 = 0.f, b0 = 0.f, c0 = 0.f;
    float a1 = 0.f, b1 = 0.f, c1 = 0.f;

    int j = 0;
    #pragma unroll 4
    for (; j + 2 <= d; j += 2) {
        const int2 e0 = __ldcs(&g_adj[abase + j]);
        const int2 e1 = __ldcs(&g_adj[abase + j + 1]);
        const float2 xv0 = *reinterpret_cast<const float2*>(x + (size_t)e0.x * IN_DIM + 2 * lane);
        const float2 xv1 = *reinterpret_cast<const float2*>(x + (size_t)e1.x * IN_DIM + 2 * lane);
        const float ev0 = __ldcs(ea + (size_t)e0.y * EDGE_DIM + lane);
        const float ev1 = __ldcs(ea + (size_t)e1.y * EDGE_DIM + lane);
        a0 += xv0.x;  b0 += xv0.y;  c0 += ev0;
        a1 += xv1.x;  b1 += xv1.y;  c1 += ev1;
    }
    if (j < d) {
        const int2 e0 = __ldcs(&g_adj[abase + j]);
        const float2 xv0 = *reinterpret_cast<const float2*>(x + (size_t)e0.x * IN_DIM + 2 * lane);
        a0 += xv0.x;  b0 += xv0.y;
        c0 += __ldcs(ea + (size_t)e0.y * EDGE_DIM + lane);
    }

    const float inv = 1.f / fmaxf((float)true_deg, 1.f);
    float* r = g_msgin + (size_t)node * 96;
    r[2 * lane]     = (a0 + a1) * inv;
    r[2 * lane + 1] = (b0 + b1) * inv;
    r[64 + lane]    = (c0 + c1) * inv;
}

// ---- tf32 helpers ----
__device__ __forceinline__ uint32_t f32_to_tf32(float f) {
    uint32_t u;
    asm("cvt.rna.tf32.f32 %0, %1;" : "=r"(u) : "f"(f));
    return u;
}
__device__ __forceinline__ void split_tf32(float f, uint32_t& hi, uint32_t& lo) {
    hi = f32_to_tf32(f);
    lo = f32_to_tf32(f - __uint_as_float(hi));
}
__device__ __forceinline__ void mma_16n8k8(
    float& c0, float& c1, float& c2, float& c3,
    uint32_t a0, uint32_t a1, uint32_t a2, uint32_t a3,
    uint32_t b0, uint32_t b1)
{
    asm("mma.sync.aligned.m16n8k8.row.col.f32.tf32.tf32.f32 "
        "{%0,%1,%2,%3}, {%4,%5,%6,%7}, {%8,%9}, {%0,%1,%2,%3};"
        : "+f"(c0), "+f"(c1), "+f"(c2), "+f"(c3)
        : "r"(a0), "r"(a1), "r"(a2), "r"(a3), "r"(b0), "r"(b1));
}

// Tensor-core GEMM, split-A-only 2xTF32 (error ~1e-4 << 1e-3 threshold).
// R15 structure: 128 thr = 2 row-groups x 2 n-halves; 16x32 per warp; NPB 32.
__global__ void __launch_bounds__(128) k_gemm(
    const float* __restrict__ x,
    const float* __restrict__ msg_w,     // [96,64]
    const float* __restrict__ msg_b,
    const float* __restrict__ self_w,    // [64,64]
    const float* __restrict__ self_b,
    float* __restrict__ out)
{
    __shared__ float s_a[NPB_G * A_STRIDE];   // 21.0 KB
    __shared__ float s_deg[NPB_G];

    const int tid = threadIdx.x;
    const int blk_node0 = blockIdx.x * NPB_G;

    // stage A tile: 32 rows x 40 float4 (coalesced, zero-padded OOB)
    for (int idx = tid; idx < NPB_G * 40; idx += 128) {
        const int row = idx / 40;
        const int c4  = idx - row * 40;
        const int node = blk_node0 + row;
        float4 v = make_float4(0.f, 0.f, 0.f, 0.f);
        if (node < N_NODES) {
            if (c4 < 16) v = *reinterpret_cast<const float4*>(x + (size_t)node * IN_DIM + c4 * 4);
            else         v = *reinterpret_cast<const float4*>(g_msgin + (size_t)node * 96 + (c4 - 16) * 4);
        }
        *reinterpret_cast<float4*>(s_a + row * A_STRIDE + c4 * 4) = v;
    }
    for (int i = tid; i < NPB_G; i += 128) {
        const int node = blk_node0 + i;
        s_deg[i] = (node < N_NODES) ? (float)g_deg[node] : 0.f;
    }
    __syncthreads();

    const int lane = tid & 31;
    const int warp = tid >> 5;
    const int rg   = warp & 1;             // row group 0..1
    const int nh   = warp >> 1;            // n-half 0..1
    const int wr   = rg * 16;
    const int gid  = lane >> 2;            // groupID 0..7
    const int tig  = lane & 3;             // threadID_in_group 0..3

    const int row0 = wr + gid;
    const int row1 = row0 + 8;
    const float m0 = (s_deg[row0] > 0.f) ? 1.f : 0.f;
    const float m1 = (s_deg[row1] > 0.f) ? 1.f : 0.f;

    // 4 n-tiles (this warp's half): cols nh*32 + n*8 + tig*2 (+1)
    float acc[4][4];
    #pragma unroll
    for (int n = 0; n < 4; ++n) {
        const int col = nh * 32 + n * 8 + tig * 2;
        acc[n][0] = self_b[col]     + m0 * msg_b[col];
        acc[n][1] = self_b[col + 1] + m0 * msg_b[col + 1];
        acc[n][2] = self_b[col]     + m1 * msg_b[col];
        acc[n][3] = self_b[col + 1] + m1 * msg_b[col + 1];
    }

    #pragma unroll 2
    for (int kt = 0; kt < 20; ++kt) {
        const int k0 = kt * 8;
        // A fragment (row-major 16x8) + split (registers only)
        const float fa0 = s_a[row0 * A_STRIDE + k0 + tig];
        const float fa1 = s_a[row1 * A_STRIDE + k0 + tig];
        const float fa2 = s_a[row0 * A_STRIDE + k0 + tig + 4];
        const float fa3 = s_a[row1 * A_STRIDE + k0 + tig + 4];
        uint32_t a0h, a0l, a1h, a1l, a2h, a2l, a3h, a3l;
        split_tf32(fa0, a0h, a0l);
        split_tf32(fa1, a1h, a1l);
        split_tf32(fa2, a2h, a2l);
        split_tf32(fa3, a3h, a3l);

        const float* wsrc = (k0 < IN_DIM) ? (self_w + k0 * OUT_DIM)
                                          : (msg_w + (k0 - IN_DIM) * OUT_DIM);
        #pragma unroll
        for (int n = 0; n < 4; ++n) {
            const int bcol = nh * 32 + n * 8 + gid;
            const float fb0 = __ldg(wsrc + tig * OUT_DIM + bcol);        // k = tig
            const float fb1 = __ldg(wsrc + (tig + 4) * OUT_DIM + bcol);  // k = tig+4
            const uint32_t b0 = f32_to_tf32(fb0);
            const uint32_t b1 = f32_to_tf32(fb1);
            // split-A 2xTF32: (a_hi + a_lo) * b_hi; residual a*b_lo ~ 1e-4
            mma_16n8k8(acc[n][0], acc[n][1], acc[n][2], acc[n][3],
                       a0h, a1h, a2h, a3h, b0, b1);
            mma_16n8k8(acc[n][0], acc[n][1], acc[n][2], acc[n][3],
                       a0l, a1l, a2l, a3l, b0, b1);
        }
    }

    const int n0g = blk_node0 + row0;
    const int n1g = blk_node0 + row1;
    #pragma unroll
    for (int n = 0; n < 4; ++n) {
        const int col = nh * 32 + n * 8 + tig * 2;
        if (n0g < N_NODES)
            *reinterpret_cast<float2*>(out + (size_t)n0g * OUT_DIM + col) =
                make_float2(acc[n][0], acc[n][1]);
        if (n1g < N_NODES)
            *reinterpret_cast<float2*>(out + (size_t)n1g * OUT_DIM + col) =
                make_float2(acc[n][2], acc[n][3]);
    }
}

extern "C" void kernel_launch(void* const* d_in, const int* in_sizes, int n_in,
                              void* d_out, int out_size) {
    // Identify inputs by element count (robust to metadata ordering):
    const float* x = 0; const void* ei = 0; const float* ea = 0;
    const float* msg_w = 0; const float* self_w = 0;
    const float* msg_b = 0; const float* self_b = 0;
    for (int i = 0; i < n_in; ++i) {
        const int sz = in_sizes[i];
        if      (sz == N_NODES * IN_DIM)              x      = (const float*)d_in[i];
        else if (sz == 2 * N_EDGES)                   ei     = d_in[i];
        else if (sz == N_EDGES * EDGE_DIM)            ea     = (const float*)d_in[i];
        else if (sz == (IN_DIM + EDGE_DIM) * OUT_DIM) msg_w  = (const float*)d_in[i];
        else if (sz == IN_DIM * OUT_DIM)              self_w = (const float*)d_in[i];
        else if (sz == OUT_DIM) {
            if (!msg_b) msg_b = (const float*)d_in[i];
            else        self_b = (const float*)d_in[i];
        }
    }
    float* out = (float*)d_out;

    k_init<<<(N_NODES + 255) / 256, 256>>>((const int*)ei);
    k_scatter<<<(N_EDGES + 255) / 256, 256>>>(ei);
    k_gather<<<(N_NODES * 32 + 255) / 256, 256>>>(x, ea);
    k_gemm<<<(N_NODES + NPB_G - 1) / NPB_G, 128>>>(x, msg_w, msg_b, self_w, self_b, out);
}